// round 1
// baseline (speedup 1.0000x reference)
#include <cuda_runtime.h>
#include <math.h>

#define NP 160000
#define NN 10000
#define FD 32
#define NH 7
#define NC 224
#define NRBF 50

// ---------------- scratch (device globals: allocation-free) ----------------
__device__ float g_hedge[FD * NP];          // column-major [f][p]
__device__ float g_logits[NP * NH];
__device__ float g_att[NP * NH];
__device__ float g_dir[NP * 3];
__device__ float g_xmix[NP * NC];           // 143 MB
__device__ int   g_counts[NN];
__device__ int   g_cursor[NN];
__device__ int   g_offsets[NN + 1];
__device__ int   g_order[NP];

// ---------------- constant memory for edge-model weights (LDCU path) ------
__constant__ float c_wmlp[64 * NRBF];
__constant__ float c_bmlp[NRBF];
__constant__ float c_we1[115 * FD];
__constant__ float c_be1[FD];
__constant__ float c_we2[FD * FD];
__constant__ float c_be2[FD];
__constant__ float c_watt[FD * NH];
__constant__ float c_batt[NH];

__device__ __forceinline__ float siluf(float z) { return z / (1.0f + __expf(-z)); }

// ---------------- CSR build ----------------
__global__ void zero_kernel() {
    int i = blockIdx.x * 256 + threadIdx.x;
    if (i < NN) { g_counts[i] = 0; g_cursor[i] = 0; }
}

__global__ void count_kernel(const int* __restrict__ pl) {
    int p = blockIdx.x * 256 + threadIdx.x;
    if (p < NP) atomicAdd(&g_counts[pl[p]], 1);
}

__global__ void scan_kernel() {
    __shared__ int sh[1024];
    int t = threadIdx.x;
    int carry = 0;
    if (t == 0) g_offsets[0] = 0;
    for (int base = 0; base < NN; base += 1024) {
        int idx = base + t;
        int val = (idx < NN) ? g_counts[idx] : 0;
        sh[t] = val;
        __syncthreads();
        for (int off = 1; off < 1024; off <<= 1) {
            int add = (t >= off) ? sh[t - off] : 0;
            __syncthreads();
            sh[t] += add;
            __syncthreads();
        }
        if (idx < NN) g_offsets[idx + 1] = carry + sh[t];
        int tot = sh[1023];
        __syncthreads();
        carry += tot;
    }
}

__global__ void scatter_kernel(const int* __restrict__ pl) {
    int p = blockIdx.x * 256 + threadIdx.x;
    if (p < NP) {
        int i = pl[p];
        int pos = g_offsets[i] + atomicAdd(&g_cursor[i], 1);
        g_order[pos] = p;
    }
}

// ---------------- edge model ----------------
// thread = pair; activations in padded smem scratch (stride 121, conflict-free);
// weights via __constant__ -> LDCU (uniform port, rt=1): sustains 2 FMA/cyc/SM.
__global__ void __launch_bounds__(128) edge_kernel(
    const float* __restrict__ h, const float* __restrict__ x,
    const int* __restrict__ pl)
{
    extern __shared__ float smem[];
    float* my = smem + threadIdx.x * 121;
    int p = blockIdx.x * 128 + threadIdx.x;   // grid exactly covers NP

    int i = pl[p], j = pl[NP + p];
    float xi0 = x[i*3], xi1 = x[i*3+1], xi2 = x[i*3+2];
    float r0 = x[j*3] - xi0, r1 = x[j*3+1] - xi1, r2 = x[j*3+2] - xi2;
    float d = sqrtf(r0*r0 + r1*r1 + r2*r2);
    float inv = 1.0f / (d + 1e-5f);
    g_dir[p*3]   = r0 * inv;
    g_dir[p*3+1] = r1 * inv;
    g_dir[p*3+2] = r2 * inv;

    // h_cat into scratch[0..63]
    const float4* hi = (const float4*)(h + i * FD);
    const float4* hj = (const float4*)(h + j * FD);
    #pragma unroll
    for (int q = 0; q < 8; q++) {
        float4 a = hi[q];
        my[4*q] = a.x; my[4*q+1] = a.y; my[4*q+2] = a.z; my[4*q+3] = a.w;
    }
    #pragma unroll
    for (int q = 0; q < 8; q++) {
        float4 a = hj[q];
        my[32+4*q] = a.x; my[32+4*q+1] = a.y; my[32+4*q+2] = a.z; my[32+4*q+3] = a.w;
    }

    // stage 1: t[50] = h_cat @ w_mlp_in + b
    float acc[NRBF];
    #pragma unroll
    for (int k = 0; k < NRBF; k++) acc[k] = c_bmlp[k];
    #pragma unroll 2
    for (int c = 0; c < 64; c++) {
        float v = my[c];
        #pragma unroll
        for (int k = 0; k < NRBF; k++) acc[k] += v * c_wmlp[c * NRBF + k];
    }
    // filt = rbf(d) * t -> scratch[64..113], d -> scratch[114]
    #pragma unroll
    for (int k = 0; k < NRBF; k++) {
        float ce = d - (float)k * (5.0f / 49.0f);
        my[64 + k] = __expf(-10.0f * ce * ce) * acc[k];
    }
    my[114] = d;

    // stage 2: u = silu(e_in @ w_e1 + b_e1)
    float a2[FD];
    #pragma unroll
    for (int k = 0; k < FD; k++) a2[k] = c_be1[k];
    #pragma unroll 2
    for (int c = 0; c < 115; c++) {
        float v = my[c];
        #pragma unroll
        for (int k = 0; k < FD; k++) a2[k] += v * c_we1[c * FD + k];
    }
    #pragma unroll
    for (int k = 0; k < FD; k++) my[k] = siluf(a2[k]);   // reuse scratch

    // stage 3: h_edge = u @ w_e2 + b_e2
    float a3[FD];
    #pragma unroll
    for (int k = 0; k < FD; k++) a3[k] = c_be2[k];
    #pragma unroll 2
    for (int c = 0; c < FD; c++) {
        float v = my[c];
        #pragma unroll
        for (int k = 0; k < FD; k++) a3[k] += v * c_we2[c * FD + k];
    }
    #pragma unroll
    for (int k = 0; k < FD; k++) {
        g_hedge[k * NP + p] = a3[k];  // column-major store
        my[k] = a3[k];
    }

    // stage 4: logits = celu(h_edge @ w_att + b_att, alpha=2)
    float a4[NH];
    #pragma unroll
    for (int k = 0; k < NH; k++) a4[k] = c_batt[k];
    #pragma unroll 2
    for (int c = 0; c < FD; c++) {
        float v = my[c];
        #pragma unroll
        for (int k = 0; k < NH; k++) a4[k] += v * c_watt[c * NH + k];
    }
    #pragma unroll
    for (int k = 0; k < NH; k++) {
        float z = a4[k];
        float cel = (z > 0.0f) ? z : 2.0f * (__expf(0.5f * z) - 1.0f);
        g_logits[p * NH + k] = cel;
    }
}

// ---------------- scatter softmax (warp per node, CSR) ----------------
__global__ void __launch_bounds__(256) softmax_kernel() {
    int node = blockIdx.x * 8 + (threadIdx.x >> 5);
    int lane = threadIdx.x & 31;
    int s = g_offsets[node], e = g_offsets[node + 1];

    float mx[NH];
    #pragma unroll
    for (int k = 0; k < NH; k++) mx[k] = -1e30f;
    for (int idx = s + lane; idx < e; idx += 32) {
        int p = g_order[idx];
        #pragma unroll
        for (int k = 0; k < NH; k++) mx[k] = fmaxf(mx[k], g_logits[p * NH + k]);
    }
    #pragma unroll
    for (int k = 0; k < NH; k++)
        #pragma unroll
        for (int off = 16; off; off >>= 1)
            mx[k] = fmaxf(mx[k], __shfl_xor_sync(0xffffffffu, mx[k], off));

    float sm[NH];
    #pragma unroll
    for (int k = 0; k < NH; k++) sm[k] = 0.0f;
    for (int idx = s + lane; idx < e; idx += 32) {
        int p = g_order[idx];
        #pragma unroll
        for (int k = 0; k < NH; k++) sm[k] += __expf(g_logits[p * NH + k] - mx[k]);
    }
    #pragma unroll
    for (int k = 0; k < NH; k++)
        #pragma unroll
        for (int off = 16; off; off >>= 1)
            sm[k] += __shfl_xor_sync(0xffffffffu, sm[k], off);

    for (int idx = s + lane; idx < e; idx += 32) {
        int p = g_order[idx];
        #pragma unroll
        for (int k = 0; k < NH; k++)
            g_att[p * NH + k] = __expf(g_logits[p * NH + k] - mx[k]) / sm[k];
    }
}

// ---------------- big GEMM: x_mixed = tanh(sem @ w_xmix) ----------------
// BM=64 pairs, N=224 full, BK=16. 256 threads, thread tile 8m x 7n.
// sem tile formed on the fly from h_edge (col-major) x att.
__global__ void __launch_bounds__(256) gemm_kernel(const float* __restrict__ wx) {
    extern __shared__ float sm[];
    float* semT = sm;              // [224][64]
    float* wbuf = sm + NC * 64;    // 3584 floats (also staging for he/att)

    int tid = threadIdx.x;
    int m0 = blockIdx.x * 64;

    // stage h_edge tile [32][64] and att tile [448] into wbuf region
    float* s_he = wbuf;            // 2048 floats
    float* s_att = wbuf + 2048;    // 448 floats
    {
        int m = tid & 63, f0 = tid >> 6;
        #pragma unroll
        for (int it = 0; it < 8; it++) {
            int f = f0 + 4 * it;
            s_he[f * 64 + m] = g_hedge[f * NP + m0 + m];
        }
    }
    for (int t2 = tid; t2 < 448; t2 += 256) s_att[t2] = g_att[m0 * NH + t2];
    __syncthreads();

    // semT[k][m] = he[k/7][m] * att[m][k%7]
    for (int idx = tid; idx < NC * 64; idx += 256) {
        int k = idx >> 6, m = idx & 63;
        semT[idx] = s_he[(k / 7) * 64 + m] * s_att[m * 7 + (k % 7)];
    }
    __syncthreads();

    int tn = tid & 31, tm = tid >> 5;
    float r[8][7];
    #pragma unroll
    for (int j = 0; j < 8; j++)
        #pragma unroll
        for (int q = 0; q < 7; q++) r[j][q] = 0.0f;

    for (int kt = 0; kt < 14; kt++) {
        __syncthreads();   // previous compute done reading wbuf
        const float4* src = (const float4*)(wx + kt * 16 * NC);
        float4* dst = (float4*)wbuf;
        for (int t4 = tid; t4 < 896; t4 += 256) dst[t4] = src[t4];
        __syncthreads();

        #pragma unroll
        for (int kk = 0; kk < 16; kk++) {
            int k = kt * 16 + kk;
            const float4* sa = (const float4*)(semT + k * 64 + tm * 8);
            float4 a0 = sa[0], a1 = sa[1];
            float a[8] = {a0.x, a0.y, a0.z, a0.w, a1.x, a1.y, a1.z, a1.w};
            float b[7];
            #pragma unroll
            for (int q = 0; q < 7; q++) b[q] = wbuf[kk * NC + tn + 32 * q];
            #pragma unroll
            for (int j = 0; j < 8; j++)
                #pragma unroll
                for (int q = 0; q < 7; q++) r[j][q] += a[j] * b[q];
        }
    }

    #pragma unroll
    for (int j = 0; j < 8; j++) {
        int p = m0 + tm * 8 + j;
        #pragma unroll
        for (int q = 0; q < 7; q++)
            g_xmix[p * NC + tn + 32 * q] = tanhf(r[j][q]);
    }
}

// ---------------- per-node aggregation + node/velocity MLPs ----------------
__global__ void __launch_bounds__(256) node_kernel(
    const float* __restrict__ h, const float* __restrict__ x, const float* __restrict__ v,
    const float* __restrict__ w_p1, const float* __restrict__ b_p1,
    const float* __restrict__ w_p2, const float* __restrict__ b_p2,
    const float* __restrict__ w_n1, const float* __restrict__ b_n1,
    const float* __restrict__ w_n2, const float* __restrict__ b_n2,
    const float* __restrict__ w_v1, const float* __restrict__ b_v1,
    const float* __restrict__ w_v2, const float* __restrict__ w_vmix,
    float* __restrict__ out)
{
    __shared__ float sh[8 * 512];
    int wid = threadIdx.x >> 5, lane = threadIdx.x & 31;
    float* ws = sh + wid * 512;   // [0..223] ns, [224..447] hsem, [448..479] he, [480..486] att
    int node = blockIdx.x * 8 + wid;
    int s = g_offsets[node], e = g_offsets[node + 1];

    int fj[7], hj[7];
    #pragma unroll
    for (int j = 0; j < 7; j++) { int c = lane + 32 * j; fj[j] = c / 7; hj[j] = c % 7; }

    float hs[7]  = {0,0,0,0,0,0,0};
    float cb0[7] = {0,0,0,0,0,0,0};
    float cb1[7] = {0,0,0,0,0,0,0};
    float cb2[7] = {0,0,0,0,0,0,0};

    for (int idx = s; idx < e; idx++) {
        int p = g_order[idx];
        ws[448 + lane] = g_hedge[lane * NP + p];
        if (lane < 7) ws[480 + lane] = g_att[p * NH + lane];
        float d0 = g_dir[p*3], d1 = g_dir[p*3+1], d2 = g_dir[p*3+2];
        __syncwarp();
        #pragma unroll
        for (int j = 0; j < 7; j++) {
            int c = lane + 32 * j;
            float xm = g_xmix[p * NC + c];
            hs[j]  += ws[448 + fj[j]] * ws[480 + hj[j]];
            cb0[j] += d0 * xm; cb1[j] += d1 * xm; cb2[j] += d2 * xm;
        }
        __syncwarp();
    }

    float rden = 1.0f / fmaxf((float)(e - s), 1.0f);
    float vp0 = 0, vp1 = 0, vp2 = 0;
    #pragma unroll
    for (int j = 0; j < 7; j++) {
        int c = lane + 32 * j;
        float m0 = cb0[j] * rden, m1 = cb1[j] * rden, m2 = cb2[j] * rden;
        ws[c] = m0*m0 + m1*m1 + m2*m2;   // norm_sq
        ws[224 + c] = hs[j];             // h_i_semantic
        float wv = __ldg(&w_vmix[c]);
        vp0 += wv * m0; vp1 += wv * m1; vp2 += wv * m2;
    }
    #pragma unroll
    for (int off = 16; off; off >>= 1) {
        vp0 += __shfl_xor_sync(0xffffffffu, vp0, off);
        vp1 += __shfl_xor_sync(0xffffffffu, vp1, off);
        vp2 += __shfl_xor_sync(0xffffffffu, vp2, off);
    }
    __syncwarp();

    // spatial MLP: silu(silu(ns @ w_p1 + b) @ w_p2 + b)
    float o1 = __ldg(&b_p1[lane]);
    for (int c = 0; c < NC; c++) o1 += ws[c] * __ldg(&w_p1[c * 32 + lane]);
    o1 = siluf(o1);
    float o2 = __ldg(&b_p2[lane]);
    for (int c = 0; c < 32; c++)
        o2 += __shfl_sync(0xffffffffu, o1, c) * __ldg(&w_p2[c * 32 + lane]);
    float hspat = siluf(o2);

    // node MLP
    float hv = h[node * 32 + lane];
    float n1 = __ldg(&b_n1[lane]);
    for (int c = 0; c < 32; c++)
        n1 += __shfl_sync(0xffffffffu, hv, c) * __ldg(&w_n1[c * 32 + lane]);
    for (int c = 0; c < NC; c++)
        n1 += ws[224 + c] * __ldg(&w_n1[(32 + c) * 32 + lane]);
    for (int c = 0; c < 32; c++)
        n1 += __shfl_sync(0xffffffffu, hspat, c) * __ldg(&w_n1[(256 + c) * 32 + lane]);
    n1 = siluf(n1);
    float n2 = __ldg(&b_n2[lane]);
    for (int c = 0; c < 32; c++)
        n2 += __shfl_sync(0xffffffffu, n1, c) * __ldg(&w_n2[c * 32 + lane]);
    float hup = hv + siluf(n2);
    out[node * 32 + lane] = hup;

    // velocity MLP
    float v1 = __ldg(&b_v1[lane]);
    for (int c = 0; c < 32; c++)
        v1 += __shfl_sync(0xffffffffu, hv, c) * __ldg(&w_v1[c * 32 + lane]);
    v1 = siluf(v1);
    float sv = v1 * __ldg(&w_v2[lane]);
    #pragma unroll
    for (int off = 16; off; off >>= 1) sv += __shfl_xor_sync(0xffffffffu, sv, off);
    float scale = 2.0f / (1.0f + __expf(-sv));

    if (lane < 3) {
        float dv = (lane == 0) ? vp0 : ((lane == 1) ? vp1 : vp2);
        float vu = scale * v[node * 3 + lane] + dv;
        out[NN * 32 + node * 3 + lane] = x[node * 3 + lane] + vu;   // x_updated
        out[NN * 32 + NN * 3 + node * 3 + lane] = vu;               // v_updated
    }
}

// ---------------- launch ----------------
extern "C" void kernel_launch(void* const* d_in, const int* in_sizes, int n_in,
                              void* d_out, int out_size)
{
    const float* h  = (const float*)d_in[0];
    const float* x  = (const float*)d_in[1];
    const float* v  = (const float*)d_in[2];
    const int*   pl = (const int*)d_in[3];

    cudaMemcpyToSymbolAsync(c_wmlp, d_in[4], 64 * NRBF * 4, 0, cudaMemcpyDeviceToDevice, 0);
    cudaMemcpyToSymbolAsync(c_bmlp, d_in[5], NRBF * 4,      0, cudaMemcpyDeviceToDevice, 0);
    cudaMemcpyToSymbolAsync(c_we1,  d_in[6], 115 * FD * 4,  0, cudaMemcpyDeviceToDevice, 0);
    cudaMemcpyToSymbolAsync(c_be1,  d_in[7], FD * 4,        0, cudaMemcpyDeviceToDevice, 0);
    cudaMemcpyToSymbolAsync(c_we2,  d_in[8], FD * FD * 4,   0, cudaMemcpyDeviceToDevice, 0);
    cudaMemcpyToSymbolAsync(c_be2,  d_in[9], FD * 4,        0, cudaMemcpyDeviceToDevice, 0);
    cudaMemcpyToSymbolAsync(c_watt, d_in[10], FD * NH * 4,  0, cudaMemcpyDeviceToDevice, 0);
    cudaMemcpyToSymbolAsync(c_batt, d_in[11], NH * 4,       0, cudaMemcpyDeviceToDevice, 0);

    int edge_smem = 128 * 121 * 4;
    int gemm_smem = (NC * 64 + 3584) * 4;
    cudaFuncSetAttribute(edge_kernel, cudaFuncAttributeMaxDynamicSharedMemorySize, edge_smem);
    cudaFuncSetAttribute(gemm_kernel, cudaFuncAttributeMaxDynamicSharedMemorySize, gemm_smem);

    zero_kernel<<<(NN + 255) / 256, 256>>>();
    count_kernel<<<(NP + 255) / 256, 256>>>(pl);
    scan_kernel<<<1, 1024>>>();
    scatter_kernel<<<(NP + 255) / 256, 256>>>(pl);

    edge_kernel<<<NP / 128, 128, edge_smem>>>(h, x, pl);
    softmax_kernel<<<NN / 8, 256>>>();
    gemm_kernel<<<NP / 64, 256, gemm_smem>>>((const float*)d_in[23]);

    node_kernel<<<NN / 8, 256>>>(
        h, x, v,
        (const float*)d_in[16], (const float*)d_in[17],   // w_p1, b_p1
        (const float*)d_in[18], (const float*)d_in[19],   // w_p2, b_p2
        (const float*)d_in[12], (const float*)d_in[13],   // w_n1, b_n1
        (const float*)d_in[14], (const float*)d_in[15],   // w_n2, b_n2
        (const float*)d_in[20], (const float*)d_in[21],   // w_v1, b_v1
        (const float*)d_in[22], (const float*)d_in[24],   // w_v2, w_vmix
        (float*)d_out);
}